// round 16
// baseline (speedup 1.0000x reference)
#include <cuda_runtime.h>
#include <cuda_bf16.h>
#include <mma.h>
#include <math.h>

using namespace nvcuda;

// Problem dims
#define SDIM 256
#define BDIM 64
#define EDIM 1024
#define VDIM 5

#define NCTA 256
#define NTHR 256

// ---------------- scratch (device globals; no allocs allowed) ----------------
#define KT_OFF   0
#define VT_OFF   16777216
#define H1_OFF   33554432
#define C1_OFF   (H1_OFF + 65536)
#define H2_OFF   (C1_OFF + 65536)
#define C2_OFF   (H2_OFF + 65536)
#define QP_OFF   (C2_OFF + 65536)              // 16 x 65536 q split-K partials
#define WOP_OFF  (QP_OFF + 16*65536)           // 16 x 65536 wo split-K partials
#define CTX_OFF  (WOP_OFF + 16*65536)
#define ATT_OFF  (CTX_OFF + 65536)
#define G1_OFF   (ATT_OFF + 65536)             // 4 x 262144 gate1 partials
#define G2_OFF   (G1_OFF + 4*262144)           // 4 x 262144 gate2 partials
// k-major bf16 split weights (hi/lo), sizes in float units (2 bf16 per float)
#define QTH_OFF  (G2_OFF + 4*262144)
#define QTL_OFF  (QTH_OFF + 524288)
#define OTH_OFF  (QTL_OFF + 524288)
#define OTL_OFF  (OTH_OFF + 524288)
#define G1TH_OFF (OTL_OFF + 524288)            // 3072 x 4096 bf16
#define G1TL_OFF (G1TH_OFF + 6291456)
#define G2TH_OFF (G1TL_OFF + 6291456)          // 2048 x 4096 bf16
#define G2TL_OFF (G2TH_OFF + 4194304)
#define BUF_TOTAL (G2TL_OFF + 4194304)

__device__ float g_buf[BUF_TOTAL];
__device__ unsigned g_bar_cnt = 0;
__device__ unsigned g_bar_gen = 0;

// ---------------- helpers ----------------
__device__ __forceinline__ float sigf(float x) { return 1.f / (1.f + expf(-x)); }
__device__ __forceinline__ void cp16(void* dst_smem, const void* src) {
    unsigned d = (unsigned)__cvta_generic_to_shared(dst_smem);
    asm volatile("cp.async.cg.shared.global [%0], [%1], 16;" :: "r"(d), "l"(src));
}
#define CP_COMMIT() asm volatile("cp.async.commit_group;" ::: "memory")
#define CP_WAIT2()  asm volatile("cp.async.wait_group 2;" ::: "memory")

// ---------------- grid barrier (all 256 CTAs co-resident) ----------------
__device__ __forceinline__ void grid_bar() {
    __threadfence();
    __syncthreads();
    if (threadIdx.x == 0) {
        volatile unsigned* vg = &g_bar_gen;
        unsigned gen = *vg;
        if (atomicAdd(&g_bar_cnt, 1u) == NCTA - 1u) {
            g_bar_cnt = 0u;
            __threadfence();
            *vg = gen + 1u;
        } else {
            while (*vg == gen) { __nanosleep(32); }
        }
    }
    __syncthreads();
}

// ---------------- setup: weight transpose + bf16 hi/lo split (ONE launch) ----------------
// dstHi/dstLo (k-major [K x N] bf16): dst[(kdst0+k)*ldd + n] = split(src[n*lds + k])
__global__ void prep_weights(const float* __restrict__ wq,   const float* __restrict__ wo,
                             const float* __restrict__ wih1, const float* __restrict__ whh1,
                             const float* __restrict__ wih2, const float* __restrict__ whh2) {
    __shared__ float tile[32][33];
    int b = blockIdx.x;
    const float* src; int lds, hiOff, loOff, ldd, kdst0, kb, nb;
    if (b < 1024)       { int r2 = b;         src = wq;   lds = 1024; hiOff = QTH_OFF;  loOff = QTL_OFF;  ldd = 1024; kdst0 = 0;    kb = r2 & 31; nb = r2 >> 5; }
    else if (b < 2048)  { int r2 = b - 1024;  src = wo;   lds = 1024; hiOff = OTH_OFF;  loOff = OTL_OFF;  ldd = 1024; kdst0 = 0;    kb = r2 & 31; nb = r2 >> 5; }
    else if (b < 10240) { int r2 = b - 2048;  src = wih1; lds = 2048; hiOff = G1TH_OFF; loOff = G1TL_OFF; ldd = 4096; kdst0 = 0;    kb = r2 & 63; nb = r2 >> 6; }
    else if (b < 14336) { int r2 = b - 10240; src = whh1; lds = 1024; hiOff = G1TH_OFF; loOff = G1TL_OFF; ldd = 4096; kdst0 = 2048; kb = r2 & 31; nb = r2 >> 5; }
    else if (b < 18432) { int r2 = b - 14336; src = wih2; lds = 1024; hiOff = G2TH_OFF; loOff = G2TL_OFF; ldd = 4096; kdst0 = 0;    kb = r2 & 31; nb = r2 >> 5; }
    else                { int r2 = b - 18432; src = whh2; lds = 1024; hiOff = G2TH_OFF; loOff = G2TL_OFF; ldd = 4096; kdst0 = 1024; kb = r2 & 31; nb = r2 >> 5; }
    int k0 = kb << 5, n0 = nb << 5;
    int tx = threadIdx.x, ty = threadIdx.y;   // 32 x 8
#pragma unroll
    for (int j = 0; j < 4; j++)
        tile[ty + j*8][tx] = src[(size_t)(n0 + ty + j*8) * lds + k0 + tx];
    __syncthreads();
    __nv_bfloat16* dh = (__nv_bfloat16*)(g_buf + hiOff);
    __nv_bfloat16* dl = (__nv_bfloat16*)(g_buf + loOff);
#pragma unroll
    for (int j = 0; j < 4; j++) {
        float v = tile[tx][ty + j*8];                    // src[n0+tx][k0+ty+8j]
        __nv_bfloat16 h = __float2bfloat16_rn(v);
        __nv_bfloat16 l = __float2bfloat16_rn(v - __bfloat162float(h));
        size_t di = (size_t)(kdst0 + k0 + ty + j*8) * ldd + n0 + tx;
        dh[di] = h; dl[di] = l;
    }
}

// ---------------- K/V precompute GEMM (fp32, unchanged from R14) ----------------
__global__ __launch_bounds__(256) void gemm_kv(const float* __restrict__ cnn,
                                               const float* __restrict__ w_qkv,
                                               const float* __restrict__ b_qkv) {
    __shared__ float As[16 * 68];
    __shared__ float Ws[16 * 68];
    int tid = threadIdx.x;
    int ty = tid >> 4, tx = tid & 15;
    int lr = tid >> 2, lk = (tid & 3) << 2;
    int n0 = blockIdx.x << 6;
    int m0 = blockIdx.y << 6;

    const float* Arow = cnn + (size_t)(m0 + lr) * EDIM + lk;
    const float* Wrow = w_qkv + (size_t)(EDIM + n0 + lr) * EDIM + lk;

    float acc[4][4];
#pragma unroll
    for (int i = 0; i < 4; i++)
#pragma unroll
        for (int j = 0; j < 4; j++) acc[i][j] = 0.f;

    float4 av = *(const float4*)(Arow);
    float4 wv = *(const float4*)(Wrow);
    for (int kt = 0; kt < EDIM; kt += 16) {
        __syncthreads();
        As[(lk)*68+lr]=av.x; As[(lk+1)*68+lr]=av.y; As[(lk+2)*68+lr]=av.z; As[(lk+3)*68+lr]=av.w;
        Ws[(lk)*68+lr]=wv.x; Ws[(lk+1)*68+lr]=wv.y; Ws[(lk+2)*68+lr]=wv.z; Ws[(lk+3)*68+lr]=wv.w;
        __syncthreads();
        if (kt + 16 < EDIM) {
            av = *(const float4*)(Arow + kt + 16);
            wv = *(const float4*)(Wrow + kt + 16);
        }
#pragma unroll
        for (int k = 0; k < 16; k++) {
            float4 a = *(const float4*)&As[k*68 + (ty<<2)];
            float4 w = *(const float4*)&Ws[k*68 + (tx<<2)];
            float ar[4] = {a.x, a.y, a.z, a.w};
            float wr[4] = {w.x, w.y, w.z, w.w};
#pragma unroll
            for (int i = 0; i < 4; i++)
#pragma unroll
                for (int j = 0; j < 4; j++) acc[i][j] = fmaf(ar[i], wr[j], acc[i][j]);
        }
    }
#pragma unroll
    for (int i = 0; i < 4; i++) {
        int mg = m0 + (ty << 2) + i;
        int s = mg >> 6, b = mg & 63;
#pragma unroll
        for (int j = 0; j < 4; j++) {
            int n = n0 + (tx << 2) + j;
            float v = acc[i][j] + b_qkv[EDIM + n];
            if (n < EDIM) {
                int h = n >> 8, d = n & 255;
                g_buf[KT_OFF + (((b << 2) + h) * 256 + d) * 256 + s] = v;   // K: [b,h,d,s]
            } else {
                int n2 = n - EDIM;
                int h = n2 >> 8, d = n2 & 255;
                g_buf[VT_OFF + (((b << 2) + h) * 256 + s) * 256 + d] = v;   // V: [b,h,s,d]
            }
        }
    }
}

// ---------------- per-step GEMM (M=64): wmma bf16x3 (hi/lo split), fp32 accum ----------------
// sA: [2 stages][hi|lo][64][32] bf16 (stage stride 4096, lo at +2048)
// sB: [4 stages][hi|lo][16][64] bf16 (stage stride 2048, lo at +1024)
__device__ __noinline__ void gemm_wmma(const __nv_bfloat16* __restrict__ WH,
                                       const __nv_bfloat16* __restrict__ WL, int N,
                                       int a0, int a1, int a2,
                                       int Kper, int outOff, int bx, int by,
                                       __nv_bfloat16* sA, __nv_bfloat16* sB)
{
    int tid = threadIdx.x;
    int n0 = bx << 6, k0 = by * Kper, nt = Kper >> 4;
    int w = tid >> 5;
    int mw = w >> 2, nw = w & 3;              // 2 m-halves x 4 n-quarters

    // B loader mapping: 256 thr = 2 matrices(hi/lo) x 16 rows x 8 chunks of 16B
    int selB = tid >> 7, rB = (tid >> 3) & 15, cB = (tid & 7) << 3;
    const __nv_bfloat16* wsrc = (selB ? WL : WH) + (size_t)(k0 + rB) * N + n0 + cB;
    __nv_bfloat16* wdst = sB + selB * 1024 + rB * 64 + cB;

    // A loader mapping: 256 thr = 64 rows x 4 chunks of 4 floats
    int rA = tid >> 2, kqA = (tid & 3) << 2;

    wmma::fragment<wmma::accumulator, 16, 16, 16, float> acc0, acc1;
    wmma::fill_fragment(acc0, 0.f);
    wmma::fill_fragment(acc1, 0.f);

    // preamble: B stages 0..2 via cp.async
#pragma unroll
    for (int s = 0; s < 3; s++) {
        if (s < nt) cp16(wdst + (s & 3) * 2048, wsrc + (size_t)(s << 4) * N);
        CP_COMMIT();
    }
    // A tile 0: load fp32, split, store stage 0
    float4 av;
    {
        int seg = k0 >> 10, kin = k0 & 1023;
        int ab = (seg == 0 ? a0 : (seg == 1 ? a1 : a2));
        av = __ldcg((const float4*)(g_buf + ab + rA * 1024 + kin + kqA));
        __nv_bfloat16* bas = sA + rA * 32 + kqA;
        float f0 = av.x, f1 = av.y, f2 = av.z, f3 = av.w;
        __nv_bfloat16 h0=__float2bfloat16_rn(f0), h1=__float2bfloat16_rn(f1),
                      h2=__float2bfloat16_rn(f2), h3=__float2bfloat16_rn(f3);
        ((__nv_bfloat162*)bas)[0] = __nv_bfloat162(h0, h1);
        ((__nv_bfloat162*)bas)[1] = __nv_bfloat162(h2, h3);
        ((__nv_bfloat162*)(bas + 2048))[0] = __nv_bfloat162(
            __float2bfloat16_rn(f0 - __bfloat162float(h0)), __float2bfloat16_rn(f1 - __bfloat162float(h1)));
        ((__nv_bfloat162*)(bas + 2048))[1] = __nv_bfloat162(
            __float2bfloat16_rn(f2 - __bfloat162float(h2)), __float2bfloat16_rn(f3 - __bfloat162float(h3)));
    }
    if (nt > 1) {   // prefetch A(1)
        int kn = k0 + 16;
        int seg = kn >> 10, kin = kn & 1023;
        int ab = (seg == 0 ? a0 : (seg == 1 ? a1 : a2));
        av = __ldcg((const float4*)(g_buf + ab + rA * 1024 + kin + kqA));
    }
    CP_WAIT2();
    __syncthreads();

    for (int t = 0; t < nt; t++) {
        if (t + 3 < nt) cp16(wdst + ((t + 3) & 3) * 2048, wsrc + (size_t)((t + 3) << 4) * N);
        CP_COMMIT();
        if (t + 1 < nt) {   // split + store A(t+1) into other stage
            __nv_bfloat16* bas = sA + ((t + 1) & 1) * 4096 + rA * 32 + kqA;
            float f0 = av.x, f1 = av.y, f2 = av.z, f3 = av.w;
            __nv_bfloat16 h0=__float2bfloat16_rn(f0), h1=__float2bfloat16_rn(f1),
                          h2=__float2bfloat16_rn(f2), h3=__float2bfloat16_rn(f3);
            ((__nv_bfloat162*)bas)[0] = __nv_bfloat162(h0, h1);
            ((__nv_bfloat162*)bas)[1] = __nv_bfloat162(h2, h3);
            ((__nv_bfloat162*)(bas + 2048))[0] = __nv_bfloat162(
                __float2bfloat16_rn(f0 - __bfloat162float(h0)), __float2bfloat16_rn(f1 - __bfloat162float(h1)));
            ((__nv_bfloat162*)(bas + 2048))[1] = __nv_bfloat162(
                __float2bfloat16_rn(f2 - __bfloat162float(h2)), __float2bfloat16_rn(f3 - __bfloat162float(h3)));
        }
        if (t + 2 < nt) {   // prefetch A(t+2)
            int kn = k0 + ((t + 2) << 4);
            int seg = kn >> 10, kin = kn & 1023;
            int ab = (seg == 0 ? a0 : (seg == 1 ? a1 : a2));
            av = __ldcg((const float4*)(g_buf + ab + rA * 1024 + kin + kqA));
        }
        // compute tile t: acc += Ahi*Bhi + Ahi*Blo + Alo*Bhi
        {
            const __nv_bfloat16* A = sA + (t & 1) * 4096;
            const __nv_bfloat16* B = sB + (t & 3) * 2048;
            wmma::fragment<wmma::matrix_a, 16, 16, 16, __nv_bfloat16, wmma::row_major> ah0, ah1, al0, al1;
            wmma::fragment<wmma::matrix_b, 16, 16, 16, __nv_bfloat16, wmma::row_major> bh, bl;
            wmma::load_matrix_sync(ah0, A + (mw * 32 + 0) * 32, 32);
            wmma::load_matrix_sync(ah1, A + (mw * 32 + 16) * 32, 32);
            wmma::load_matrix_sync(al0, A + 2048 + (mw * 32 + 0) * 32, 32);
            wmma::load_matrix_sync(al1, A + 2048 + (mw * 32 + 16) * 32, 32);
            wmma::load_matrix_sync(bh, B + nw * 16, 64);
            wmma::load_matrix_sync(bl, B + 1024 + nw * 16, 64);
            wmma::mma_sync(acc0, ah0, bh, acc0);
            wmma::mma_sync(acc1, ah1, bh, acc1);
            wmma::mma_sync(acc0, ah0, bl, acc0);
            wmma::mma_sync(acc1, ah1, bl, acc1);
            wmma::mma_sync(acc0, al0, bh, acc0);
            wmma::mma_sync(acc1, al1, bh, acc1);
        }
        CP_WAIT2();
        __syncthreads();
    }

    float* op = g_buf + outOff + (size_t)(by << 6) * N + n0 + nw * 16;
    wmma::store_matrix_sync(op + (size_t)(mw * 32) * N,      acc0, N, wmma::mem_row_major);
    wmma::store_matrix_sync(op + (size_t)(mw * 32 + 16) * N, acc1, N, wmma::mem_row_major);
}

// ---------------- attention: one (b,h) per CTA; fp32 K/V; shuffle softmax ----------------
__device__ __noinline__ void attn_dev(const float* __restrict__ b_qkv, float* sh) {
    float* qs   = sh;          // 256
    float* pr   = sh + 256;    // 256
    float* wred = sh + 512;    // 8
    int t = threadIdx.x;
    int lane = t & 31, w = t >> 5;
    int bh = blockIdx.x;              // 0..255
    int b = bh >> 2, h = bh & 3;
    int e = (h << 8) + t;
    float qv = b_qkv[e];
#pragma unroll
    for (int sp = 0; sp < 16; sp++) qv += __ldcg(g_buf + QP_OFF + sp * 65536 + (b << 10) + e);
    qs[t] = qv * 0.0625f;             // fold 1/sqrt(256)
    __syncthreads();

    const float* Kb = g_buf + KT_OFF + bh * 65536;
    float acc = 0.f;
#pragma unroll 16
    for (int d = 0; d < 256; d++) acc += qs[d] * Kb[(d << 8) + t];

    float m = acc;
#pragma unroll
    for (int off = 16; off; off >>= 1) m = fmaxf(m, __shfl_xor_sync(0xffffffffu, m, off));
    if (lane == 0) wred[w] = m;
    __syncthreads();
    float mx = wred[0];
#pragma unroll
    for (int j = 1; j < 8; j++) mx = fmaxf(mx, wred[j]);
    float ex = expf(acc - mx);
    float s = ex;
#pragma unroll
    for (int off = 16; off; off >>= 1) s += __shfl_xor_sync(0xffffffffu, s, off);
    __syncthreads();
    if (lane == 0) wred[w] = s;
    __syncthreads();
    float tot = wred[0];
#pragma unroll
    for (int j = 1; j < 8; j++) tot += wred[j];
    pr[t] = ex * (1.f / tot);
    __syncthreads();

    const float* Vb = g_buf + VT_OFF + bh * 65536;
    float c = 0.f;
#pragma unroll 16
    for (int s2 = 0; s2 < 256; s2++) c += pr[s2] * Vb[(s2 << 8) + t];
    g_buf[ATT_OFF + (b << 10) + e] = c;
}

// ---------------- w_o split-K reduce + bias (16 slices) ----------------
__device__ __forceinline__ void wored_dev(const float* __restrict__ b_o) {
    int idx = blockIdx.x * NTHR + threadIdx.x;    // exactly 65536
    int e = idx & 1023;
    float v = b_o[e];
#pragma unroll
    for (int sp = 0; sp < 16; sp++) v += __ldcg(g_buf + WOP_OFF + sp * 65536 + idx);
    g_buf[CTX_OFF + idx] = v;
}

// ---------------- LSTM cell: sums 4 split-K gate partials + biases ----------------
__device__ __noinline__ void cell_dev(int gOff, const float* __restrict__ bi, const float* __restrict__ bh,
                                      int hOff, int cOff) {
    int idx = blockIdx.x * NTHR + threadIdx.x;    // exactly 65536 = (b,e)
    int b = idx >> 10, e = idx & 1023;
    const float* gb = g_buf + gOff + (size_t)b * 4096;
    float gi = bi[e]        + bh[e];
    float gf = bi[1024 + e] + bh[1024 + e];
    float gg = bi[2048 + e] + bh[2048 + e];
    float go = bi[3072 + e] + bh[3072 + e];
#pragma unroll
    for (int sp = 0; sp < 4; sp++) {
        const float* g = gb + sp * 262144;
        gi += __ldcg(g + e);
        gf += __ldcg(g + 1024 + e);
        gg += __ldcg(g + 2048 + e);
        go += __ldcg(g + 3072 + e);
    }
    float c = __ldcg(g_buf + cOff + idx);
    float cn = sigf(gf) * c + sigf(gi) * tanhf(gg);
    g_buf[cOff + idx] = cn;
    g_buf[hOff + idx] = sigf(go) * tanhf(cn);
}

// ---------------- output head (CTAs 0..63, 5 warps used) ----------------
__device__ __forceinline__ void head_dev(const float* __restrict__ w_out, const float* __restrict__ b_out,
                                         float* __restrict__ out, int t) {
    if (blockIdx.x < 64 && threadIdx.x < 160) {
        int b = blockIdx.x;
        int w = threadIdx.x >> 5, lane = threadIdx.x & 31;
        const float* hb = g_buf + H2_OFF + (b << 10);
        const float* wr = w_out + w * 1024;
        float a = 0.f;
        for (int j = lane; j < 1024; j += 32) a += __ldcg(hb + j) * wr[j];
#pragma unroll
        for (int off = 16; off; off >>= 1) a += __shfl_down_sync(0xffffffffu, a, off);
        if (lane == 0) {
            a += b_out[w];
            if (w >= 2) a = 1.f / (1.f + expf(-a));
            out[((t << 6) + b) * VDIM + w] = a;
        }
    }
}

// ---------------- persistent main kernel: whole 256-step recurrence ----------------
__global__ void __launch_bounds__(NTHR, 2) main_kernel(
    const float* __restrict__ b_qkv, const float* __restrict__ b_o,
    const float* __restrict__ b_ih1, const float* __restrict__ b_hh1,
    const float* __restrict__ b_ih2, const float* __restrict__ b_hh2,
    const float* __restrict__ w_out, const float* __restrict__ b_out,
    float* __restrict__ out)
{
    __shared__ __align__(16) __nv_bfloat16 sAB[16384];   // 32 KB: A 8192 + B 8192
    __nv_bfloat16* sA = sAB;
    __nv_bfloat16* sB = sAB + 8192;
    float* shf = (float*)sAB;                            // attn scratch (aliased)
    int r = blockIdx.x;

    // zero recurrent state (h1,c1,h2,c2)
    for (int i = r * NTHR + threadIdx.x; i < 4 * BDIM * EDIM; i += NCTA * NTHR)
        g_buf[H1_OFF + i] = 0.f;
    grid_bar();

    const __nv_bfloat16* QTH  = (const __nv_bfloat16*)(g_buf + QTH_OFF);
    const __nv_bfloat16* QTL  = (const __nv_bfloat16*)(g_buf + QTL_OFF);
    const __nv_bfloat16* OTH  = (const __nv_bfloat16*)(g_buf + OTH_OFF);
    const __nv_bfloat16* OTL  = (const __nv_bfloat16*)(g_buf + OTL_OFF);
    const __nv_bfloat16* G1TH = (const __nv_bfloat16*)(g_buf + G1TH_OFF);
    const __nv_bfloat16* G1TL = (const __nv_bfloat16*)(g_buf + G1TL_OFF);
    const __nv_bfloat16* G2TH = (const __nv_bfloat16*)(g_buf + G2TH_OFF);
    const __nv_bfloat16* G2TL = (const __nv_bfloat16*)(g_buf + G2TL_OFF);

    for (int t = 0; t < SDIM; t++) {
        // phase 1: head(t-1) overlapped with q projection (both read finalized h2)
        if (t > 0) head_dev(w_out, b_out, out, t - 1);
        gemm_wmma(QTH, QTL, 1024, H2_OFF, H2_OFF, H2_OFF, 64, QP_OFF, r & 15, r >> 4, sA, sB);
        grid_bar();
        // phase 2: attention (sums 16 q partials + b_q)
        attn_dev(b_qkv, shf);
        grid_bar();
        // phase 3: wo partials = att @ w_o^T
        gemm_wmma(OTH, OTL, 1024, ATT_OFF, ATT_OFF, ATT_OFF, 64, WOP_OFF, r & 15, r >> 4, sA, sB);
        grid_bar();
        // phase 4: ctx = sum of 16 partials + b_o
        wored_dev(b_o);
        grid_bar();
        // phase 5: gates1 = [h2|ctx|h1] @ G1T   (K=3072, 4-way split)
        gemm_wmma(G1TH, G1TL, 4096, H2_OFF, CTX_OFF, H1_OFF, 768, G1_OFF, r >> 2, r & 3, sA, sB);
        grid_bar();
        // phase 6: LSTM cell 1
        cell_dev(G1_OFF, b_ih1, b_hh1, H1_OFF, C1_OFF);
        grid_bar();
        // phase 7: gates2 = [h1new|h2prev] @ G2T   (K=2048, 4-way split)
        gemm_wmma(G2TH, G2TL, 4096, H1_OFF, H2_OFF, H2_OFF, 512, G2_OFF, r >> 2, r & 3, sA, sB);
        grid_bar();
        // phase 8: LSTM cell 2 (writes new h2)
        cell_dev(G2_OFF, b_ih2, b_hh2, H2_OFF, C2_OFF);
        grid_bar();
    }
    head_dev(w_out, b_out, out, SDIM - 1);
}

// ---------------- host ----------------
extern "C" void kernel_launch(void* const* d_in, const int* in_sizes, int n_in,
                              void* d_out, int out_size) {
    const float* cnn    = (const float*)d_in[0];
    const float* w_qkv  = (const float*)d_in[1];
    const float* b_qkv  = (const float*)d_in[2];
    const float* w_o    = (const float*)d_in[3];
    const float* b_o    = (const float*)d_in[4];
    const float* w_ih1  = (const float*)d_in[5];
    const float* w_hh1  = (const float*)d_in[6];
    const float* b_ih1  = (const float*)d_in[7];
    const float* b_hh1  = (const float*)d_in[8];
    const float* w_ih2  = (const float*)d_in[9];
    const float* w_hh2  = (const float*)d_in[10];
    const float* b_ih2  = (const float*)d_in[11];
    const float* b_hh2  = (const float*)d_in[12];
    const float* w_out  = (const float*)d_in[13];
    const float* b_out  = (const float*)d_in[14];
    float* out = (float*)d_out;

    // setup: bf16 hi/lo k-major weights (1 launch), fp32 K/V (1 launch)
    prep_weights<<<22528, dim3(32, 8)>>>(w_qkv, w_o, w_ih1, w_hh1, w_ih2, w_hh2);
    gemm_kv<<<dim3(32, 256), 256>>>(cnn, w_qkv, b_qkv);

    // entire recurrence in one persistent kernel (256 co-resident CTAs, 2/SM)
    main_kernel<<<NCTA, NTHR>>>(b_qkv, b_o,
                                b_ih1, b_hh1, b_ih2, b_hh2,
                                w_out, b_out, out);
}